// round 5
// baseline (speedup 1.0000x reference)
#include <cuda_runtime.h>

#define NP     16384
#define CIN    128
#define COUT   256
#define KK     20
#define WCOLS  512
#define QPB    8
#define KTP    1024      /* pairs per knn smem tile -> 2048 candidates, 32KB */
#define NSLICE 8         /* candidate slices for the filter kernel */
#define CAP    1024      /* survivor buffer entries per query */

// ---- scratch (no allocations allowed: __device__ globals) ----
__device__ float4 g_cand[NP];          // {x,y,z,|p|^2/2}
__device__ float4 g_A[NP/2];           // pair-SoA {x0,x1,y0,y1}
__device__ float4 g_B[NP/2];           // pair-SoA {z0,z1,-w0,-w1}
__device__ float  g_thr1[NP];          // exact 21st-best score among first 2048 cands
__device__ int    g_cnt[NP];           // survivor cursor per query
__device__ unsigned long long g_buf[(size_t)CAP * NP];  // (score<<32|idx), lane-interleaved
__device__ int    g_knn[NP * KK];
__device__ float  g_W2[CIN * WCOLS];
__device__ float  g_AB[(size_t)NP * WCOLS];   // [:,0:256)=A(+bias), [:,256:512)=B
__device__ float  g_sel[(size_t)NP * COUT];
__device__ double g_sumD[COUT];
__device__ double g_sumsqD[COUT];
__device__ float  g_scale[COUT];
__device__ float  g_shift[COUT];

// ---------- packed f32x2 helpers ----------
__device__ __forceinline__ unsigned long long ffma2(unsigned long long a,
                                                    unsigned long long b,
                                                    unsigned long long c) {
    unsigned long long d;
    asm("fma.rn.f32x2 %0, %1, %2, %3;" : "=l"(d) : "l"(a), "l"(b), "l"(c));
    return d;
}
__device__ __forceinline__ unsigned long long bcast2(float x) {
    unsigned long long r;
    asm("mov.b64 %0, {%1, %1};" : "=l"(r) : "f"(x));
    return r;
}
__device__ __forceinline__ void unpack2(unsigned long long v, float& lo, float& hi) {
    asm("mov.b64 {%0, %1}, %2;" : "=f"(lo), "=f"(hi) : "l"(v));
}
__device__ __forceinline__ unsigned long long d_as_ll(double d) {
    return __double_as_longlong(d);
}

// sorted-ascending 21-slot merge-insert (drops current min); branchless
__device__ __forceinline__ void merge21(float (&ss)[21], float sv) {
#pragma unroll
    for (int t = 0; t < 20; t++) ss[t] = fmaxf(ss[t], fminf(sv, ss[t+1]));
    ss[20] = fmaxf(ss[20], sv);
}

// 8 scores (4 packed pairs) from smem tiles
__device__ __forceinline__ void score8(float* s, const double2* tA, const double2* tB, int p,
                                       unsigned long long mx, unsigned long long my,
                                       unsigned long long mz) {
#pragma unroll
    for (int w = 0; w < 4; w++) {
        double2 a = tA[p + w];
        double2 b = tB[p + w];
        unsigned long long t0 = ffma2(mz, d_as_ll(b.x), d_as_ll(b.y));  // z*mz - w
        t0 = ffma2(my, d_as_ll(a.y), t0);
        t0 = ffma2(mx, d_as_ll(a.x), t0);
        unpack2(t0, s[2*w], s[2*w+1]);
    }
}

// ---- prep: candidates (AoS + pair-SoA), W rearrange, counters/stat zeroing ----
__global__ void prep_kernel(const float* __restrict__ pos, const float* __restrict__ W) {
    int t = blockIdx.x * blockDim.x + threadIdx.x;
    if (t < NP) {
        float x = pos[3*t+0], y = pos[3*t+1], z = pos[3*t+2];
        g_cand[t] = make_float4(x, y, z, 0.5f*(x*x + y*y + z*z));
        g_cnt[t] = 0;
    }
    if (t < NP/2) {
        int j0 = 2*t, j1 = 2*t + 1;
        float x0 = pos[3*j0+0], y0 = pos[3*j0+1], z0 = pos[3*j0+2];
        float x1 = pos[3*j1+0], y1 = pos[3*j1+1], z1 = pos[3*j1+2];
        float w0 = 0.5f*(x0*x0 + y0*y0 + z0*z0);
        float w1 = 0.5f*(x1*x1 + y1*y1 + z1*z1);
        g_A[t] = make_float4(x0, x1, y0, y1);
        g_B[t] = make_float4(z0, z1, -w0, -w1);
    }
    if (t < CIN * WCOLS) {
        int kk = t >> 9;
        int c  = t & 511;
        g_W2[t] = (c < COUT) ? W[kk*COUT + c] : W[(kk + CIN)*COUT + (c - COUT)];
    }
    if (t < COUT) { g_sumD[t] = 0.0; g_sumsqD[t] = 0.0; }
}

// ---- knn threshold: exact 21st-best score among candidates [0,2048) ----
__global__ void knn_thresh_kernel() {
    __shared__ double2 tA[KTP];
    __shared__ double2 tB[KTP];
    const int q = blockIdx.x * blockDim.x + threadIdx.x;
    const float4 me = g_cand[q];
    const unsigned long long mx = bcast2(me.x), my = bcast2(me.y), mz = bcast2(me.z);
    const float NEG = -3.0e38f;

    for (int l = threadIdx.x; l < KTP; l += blockDim.x) {
        tA[l] = ((const double2*)g_A)[l];
        tB[l] = ((const double2*)g_B)[l];
    }
    __syncthreads();

    float ss[21];
#pragma unroll
    for (int t = 0; t < 21; t++) ss[t] = NEG;

    // stage 1: candidates [0,256) unconditional merges -> thr0
    for (int p = 0; p < 128; p += 4) {
        float s[8];
        score8(s, tA, tB, p, mx, my, mz);
#pragma unroll
        for (int u = 0; u < 8; u++) {
            float sv = (2*p + u != q) ? s[u] : NEG;
            merge21(ss, sv);
        }
    }
    const float thr0 = ss[0];

    // stage 2: [256,2048) buffered survivors, then merge -> thr1 (sample's 21st)
    float loc[64];
    int cnt = 0;
    for (int p = 128; p < KTP; p += 4) {
        float s[8];
        score8(s, tA, tB, p, mx, my, mz);
        const int jb = 2*p;
#pragma unroll
        for (int u = 0; u < 8; u++) {
            int j = jb + u;
            if (s[u] > thr0 && j != q && cnt < 64) { loc[cnt] = s[u]; cnt++; }
        }
    }
    for (int m = 0; m < cnt; m++) merge21(ss, loc[m]);
    // if loc overflowed (cnt==64, P~0), thr1 may be slightly high; rescan exact then
    if (cnt == 64) {
        for (int t = 0; t < 21; t++) ss[t] = NEG;
        for (int p = 0; p < KTP; p += 4) {
            float s[8];
            score8(s, tA, tB, p, mx, my, mz);
#pragma unroll
            for (int u = 0; u < 8; u++) {
                float sv = (2*p + u != q) ? s[u] : NEG;
                merge21(ss, sv);
            }
        }
    }
    g_thr1[q] = ss[0];
}

// ---- knn filter: full scan, candidate-sliced; survivors appended via atomics ----
__global__ void knn_filter_kernel() {
    __shared__ double2 tA[KTP];
    __shared__ double2 tB[KTP];
    const int q = blockIdx.x * blockDim.x + threadIdx.x;
    const int pb0 = blockIdx.y * (NP/2/NSLICE);               // pair base of slice
    const float4 me = g_cand[q];
    const unsigned long long mx = bcast2(me.x), my = bcast2(me.y), mz = bcast2(me.z);
    const float thr1 = g_thr1[q];

    for (int l = threadIdx.x; l < KTP; l += blockDim.x) {
        tA[l] = ((const double2*)g_A)[pb0 + l];
        tB[l] = ((const double2*)g_B)[pb0 + l];
    }
    __syncthreads();

    const int jb0 = 2*pb0;
    for (int p = 0; p < KTP; p += 4) {
        float s[8];
        score8(s, tA, tB, p, mx, my, mz);
        const int jb = jb0 + 2*p;
#pragma unroll
        for (int u = 0; u < 8; u++) {
            int j = jb + u;
            if (s[u] > thr1 && j != q) {                      // predicated, voteless
                int slot = atomicAdd(&g_cnt[q], 1);
                if (slot < CAP)
                    g_buf[(size_t)slot * NP + q] =
                        ((unsigned long long)__float_as_uint(s[u]) << 32) | (unsigned)j;
            }
        }
    }
}

// ---- knn final: exact top-20 from survivor buffer ----
__global__ void knn_final_kernel() {
    const int q = blockIdx.x * blockDim.x + threadIdx.x;
    const float NEG = -3.0e38f;
    int cnt = g_cnt[q];
    if (cnt > CAP) cnt = CAP;

    float tt[21];
#pragma unroll
    for (int t = 0; t < 21; t++) tt[t] = NEG;
    for (int m = 0; m < cnt; m++) {
        float sv = __uint_as_float((unsigned)(g_buf[(size_t)m * NP + q] >> 32));
        merge21(tt, sv);
    }
    const float t21 = tt[0];

    int out = 0;
    for (int m = 0; m < cnt && out < KK; m++) {               // strictly above 21st
        unsigned long long e = g_buf[(size_t)m * NP + q];
        if (__uint_as_float((unsigned)(e >> 32)) > t21)
            g_knn[q*KK + (out++)] = (int)(e & 0xffffffffu);
    }
    for (int m = 0; m < cnt && out < KK; m++) {               // ties at 21st
        unsigned long long e = g_buf[(size_t)m * NP + q];
        if (__uint_as_float((unsigned)(e >> 32)) == t21)
            g_knn[q*KK + (out++)] = (int)(e & 0xffffffffu);
    }
    if (out < KK) {  // exact-tie-at-thr1 fallback: essentially never taken
        const float4 me = g_cand[q];
        const float thr1 = g_thr1[q];
        for (int j = 0; j < NP && out < KK; j++) {
            if (j == q) continue;
            float4 c = g_cand[j];
            float sv = fmaf(me.x, c.x, fmaf(me.y, c.y, fmaf(me.z, c.z, -c.w)));
            if (sv == thr1) g_knn[q*KK + (out++)] = j;
        }
    }
}

// ---- SGEMM: AB[16384,512] = X[16384,128] @ W2[128,512]  (+bias on cols<256) ----
__global__ void gemm_kernel(const float* __restrict__ X, const float* __restrict__ bias) {
    __shared__ float As[8][128];
    __shared__ float Bs[8][128];
    const int tid = threadIdx.x;
    const int m0 = blockIdx.y * 128;
    const int n0 = blockIdx.x * 128;
    const int tx = tid & 15;
    const int ty = tid >> 4;
    const int lam = tid >> 1;
    const int lak = (tid & 1) * 4;
    const int lbr = tid >> 5;
    const int lbc = (tid & 31) * 4;

    float acc[8][8];
#pragma unroll
    for (int i = 0; i < 8; i++)
#pragma unroll
        for (int j = 0; j < 8; j++) acc[i][j] = 0.0f;

    for (int kb = 0; kb < CIN; kb += 8) {
        float4 av = *(const float4*)&X[(size_t)(m0 + lam)*CIN + kb + lak];
        float4 bv = *(const float4*)&g_W2[(kb + lbr)*WCOLS + n0 + lbc];
        __syncthreads();
        As[lak+0][lam] = av.x;
        As[lak+1][lam] = av.y;
        As[lak+2][lam] = av.z;
        As[lak+3][lam] = av.w;
        *(float4*)&Bs[lbr][lbc] = bv;
        __syncthreads();
#pragma unroll
        for (int k = 0; k < 8; k++) {
            float a[8], bb[8];
            *(float4*)&a[0]  = *(const float4*)&As[k][ty*8];
            *(float4*)&a[4]  = *(const float4*)&As[k][ty*8 + 4];
            *(float4*)&bb[0] = *(const float4*)&Bs[k][tx*8];
            *(float4*)&bb[4] = *(const float4*)&Bs[k][tx*8 + 4];
#pragma unroll
            for (int i = 0; i < 8; i++)
#pragma unroll
                for (int j = 0; j < 8; j++)
                    acc[i][j] = fmaf(a[i], bb[j], acc[i][j]);
        }
    }
    const bool addb = (n0 < COUT);
#pragma unroll
    for (int i = 0; i < 8; i++) {
        int row = m0 + ty*8 + i;
#pragma unroll
        for (int j = 0; j < 8; j += 4) {
            int col = n0 + tx*8 + j;
            float4 v;
            v.x = acc[i][j+0] + (addb ? bias[col+0] : 0.0f);
            v.y = acc[i][j+1] + (addb ? bias[col+1] : 0.0f);
            v.z = acc[i][j+2] + (addb ? bias[col+2] : 0.0f);
            v.w = acc[i][j+3] + (addb ? bias[col+3] : 0.0f);
            *(float4*)&g_AB[(size_t)row*WCOLS + col] = v;
        }
    }
}

// ---- fused edge pass: per (i,c) extreme over neighbors + channel sum/sumsq ----
__global__ void edge_kernel(const float* __restrict__ gamma) {
    const int c  = threadIdx.x;
    const int i0 = blockIdx.x * QPB;
    const bool useMax = (gamma[c] >= 0.0f);
    float psum = 0.0f, psumsq = 0.0f;
    for (int g = 0; g < QPB; g++) {
        const int i = i0 + g;
        const float a = g_AB[(size_t)i*WCOLS + c];
        float best = useMax ? -3.0e38f : 3.0e38f;
#pragma unroll
        for (int k = 0; k < KK; k++) {
            int j = g_knn[i*KK + k];
            float h = a + g_AB[(size_t)j*WCOLS + COUT + c];
            psum += h;
            psumsq = fmaf(h, h, psumsq);
            best = useMax ? fmaxf(best, h) : fminf(best, h);
        }
        g_sel[(size_t)i*COUT + c] = best;
    }
    atomicAdd(&g_sumD[c], (double)psum);
    atomicAdd(&g_sumsqD[c], (double)psumsq);
}

// ---- BN stats -> per-channel scale/shift ----
__global__ void finalize_kernel(const float* __restrict__ gamma, const float* __restrict__ beta) {
    int c = threadIdx.x;
    const double inv = 1.0 / (double)(NP * KK);
    double m  = g_sumD[c] * inv;
    double v  = g_sumsqD[c] * inv - m*m;
    float sc = gamma[c] * rsqrtf((float)v + 1e-5f);
    g_scale[c] = sc;
    g_shift[c] = beta[c] - (float)m * sc;
}

// ---- epilogue: normalize selected extreme + LeakyReLU ----
__global__ void out_kernel(float* __restrict__ out) {
    int t = blockIdx.x * blockDim.x + threadIdx.x;
    int c = t & (COUT - 1);
    float h = fmaf(g_sel[t], g_scale[c], g_shift[c]);
    out[t] = (h >= 0.0f) ? h : 0.2f*h;
}

extern "C" void kernel_launch(void* const* d_in, const int* in_sizes, int n_in,
                              void* d_out, int out_size) {
    const float* pos   = (const float*)d_in[0];
    const float* x     = (const float*)d_in[1];
    const float* W     = (const float*)d_in[2];
    const float* b     = (const float*)d_in[3];
    const float* gamma = (const float*)d_in[4];
    const float* beta  = (const float*)d_in[5];
    float* out = (float*)d_out;

    prep_kernel<<<256, 256>>>(pos, W);                         // 0
    knn_thresh_kernel<<<NP / 256, 256>>>();                    // 1
    knn_filter_kernel<<<dim3(NP / 256, NSLICE), 256>>>();      // 2
    gemm_kernel<<<dim3(WCOLS / 128, NP / 128), 256>>>(x, b);   // 3 (ncu slot)
    knn_final_kernel<<<NP / 256, 256>>>();                     // 4
    edge_kernel<<<NP / QPB, 256>>>(gamma);                     // 5
    finalize_kernel<<<1, COUT>>>(gamma, beta);                 // 6
    out_kernel<<<(NP * COUT) / 256, 256>>>(out);               // 7
}

// round 6
// speedup vs baseline: 1.4745x; 1.4745x over previous
#include <cuda_runtime.h>

#define NP     16384
#define CIN    128
#define COUT   256
#define KK     20
#define WCOLS  512
#define QPB    8
#define NSLICE 8         /* candidate slices for the filter kernel */
#define KTP    1024      /* pairs per slice tile -> 2048 candidates, 32KB smem */
#define SUBCAP 128       /* survivor entries per (query, slice) */
#define TCAP   256       /* thresh stage-2 buffer rows (reuses g_buf rows [0,256)) */

// ---- scratch (no allocations allowed: __device__ globals) ----
__device__ float4 g_cand[NP];          // {x,y,z,|p|^2/2}
__device__ float4 g_A[NP/2];           // pair-SoA {x0,x1,y0,y1}
__device__ float4 g_B[NP/2];           // pair-SoA {z0,z1,-w0,-w1}
__device__ float  g_thr1[NP];          // exact 21st-best score among first 2048 cands
__device__ int    g_cntS[NSLICE * NP]; // survivor count per (slice, query)
__device__ unsigned long long g_buf[(size_t)(NSLICE*SUBCAP) * NP]; // (score<<32|idx), lane-interleaved
__device__ int    g_knn[NP * KK];
__device__ float  g_W2[CIN * WCOLS];
__device__ float  g_AB[(size_t)NP * WCOLS];   // [:,0:256)=A(+bias), [:,256:512)=B
__device__ float  g_sel[(size_t)NP * COUT];
__device__ double g_sumD[COUT];
__device__ double g_sumsqD[COUT];
__device__ float  g_scale[COUT];
__device__ float  g_shift[COUT];

// ---------- packed f32x2 helpers ----------
__device__ __forceinline__ unsigned long long ffma2(unsigned long long a,
                                                    unsigned long long b,
                                                    unsigned long long c) {
    unsigned long long d;
    asm("fma.rn.f32x2 %0, %1, %2, %3;" : "=l"(d) : "l"(a), "l"(b), "l"(c));
    return d;
}
__device__ __forceinline__ unsigned long long bcast2(float x) {
    unsigned long long r;
    asm("mov.b64 %0, {%1, %1};" : "=l"(r) : "f"(x));
    return r;
}
__device__ __forceinline__ void unpack2(unsigned long long v, float& lo, float& hi) {
    asm("mov.b64 {%0, %1}, %2;" : "=f"(lo), "=f"(hi) : "l"(v));
}
__device__ __forceinline__ unsigned long long d_as_ll(double d) {
    return __double_as_longlong(d);
}

// sorted-ascending 21-slot merge-insert (drops current min); branchless
__device__ __forceinline__ void merge21(float (&ss)[21], float sv) {
#pragma unroll
    for (int t = 0; t < 20; t++) ss[t] = fmaxf(ss[t], fminf(sv, ss[t+1]));
    ss[20] = fmaxf(ss[20], sv);
}

// 8 scores (4 packed pairs) from smem tiles
__device__ __forceinline__ void score8(float* s, const double2* tA, const double2* tB, int p,
                                       unsigned long long mx, unsigned long long my,
                                       unsigned long long mz) {
#pragma unroll
    for (int w = 0; w < 4; w++) {
        double2 a = tA[p + w];
        double2 b = tB[p + w];
        unsigned long long t0 = ffma2(mz, d_as_ll(b.x), d_as_ll(b.y));  // z*mz - w
        t0 = ffma2(my, d_as_ll(a.y), t0);
        t0 = ffma2(mx, d_as_ll(a.x), t0);
        unpack2(t0, s[2*w], s[2*w+1]);
    }
}

__device__ __forceinline__ unsigned long long packSI(float s, int j) {
    return ((unsigned long long)__float_as_uint(s) << 32) | (unsigned)j;
}
__device__ __forceinline__ float scoreOf(unsigned long long e) {
    return __uint_as_float((unsigned)(e >> 32));
}

// ---- prep: candidates (AoS + pair-SoA), W rearrange, stat zeroing ----
__global__ void prep_kernel(const float* __restrict__ pos, const float* __restrict__ W) {
    int t = blockIdx.x * blockDim.x + threadIdx.x;
    if (t < NP) {
        float x = pos[3*t+0], y = pos[3*t+1], z = pos[3*t+2];
        g_cand[t] = make_float4(x, y, z, 0.5f*(x*x + y*y + z*z));
    }
    if (t < NP/2) {
        int j0 = 2*t, j1 = 2*t + 1;
        float x0 = pos[3*j0+0], y0 = pos[3*j0+1], z0 = pos[3*j0+2];
        float x1 = pos[3*j1+0], y1 = pos[3*j1+1], z1 = pos[3*j1+2];
        float w0 = 0.5f*(x0*x0 + y0*y0 + z0*z0);
        float w1 = 0.5f*(x1*x1 + y1*y1 + z1*z1);
        g_A[t] = make_float4(x0, x1, y0, y1);
        g_B[t] = make_float4(z0, z1, -w0, -w1);
    }
    if (t < CIN * WCOLS) {
        int kk = t >> 9;
        int c  = t & 511;
        g_W2[t] = (c < COUT) ? W[kk*COUT + c] : W[(kk + CIN)*COUT + (c - COUT)];
    }
    if (t < COUT) { g_sumD[t] = 0.0; g_sumsqD[t] = 0.0; }
}

// ---- knn threshold: exact 21st-best score among candidates [0,2048) ----
// Stage 1: unconditional top-21 merges over [0,512) -> thr0.
// Stage 2: [512,2048) survivors (E~63) buffered to g_buf via predicated stores
//          (no atomics, no votes), merged -> exact 21st of the 2048-sample.
__global__ void knn_thresh_kernel() {
    __shared__ double2 tA[KTP];
    __shared__ double2 tB[KTP];
    const int q = blockIdx.x * blockDim.x + threadIdx.x;
    const float4 me = g_cand[q];
    const unsigned long long mx = bcast2(me.x), my = bcast2(me.y), mz = bcast2(me.z);
    const float NEG = -3.0e38f;

    for (int l = threadIdx.x; l < KTP; l += blockDim.x) {
        tA[l] = ((const double2*)g_A)[l];
        tB[l] = ((const double2*)g_B)[l];
    }
    __syncthreads();

    float ss[21];
#pragma unroll
    for (int t = 0; t < 21; t++) ss[t] = NEG;

    // stage 1: candidates [0,512) unconditional merges
    for (int p = 0; p < 256; p += 4) {
        float s[8];
        score8(s, tA, tB, p, mx, my, mz);
#pragma unroll
        for (int u = 0; u < 8; u++) {
            float sv = (2*p + u != q) ? s[u] : NEG;
            merge21(ss, sv);
        }
    }
    const float thr0 = ss[0];

    // stage 2: [512,2048) predicated buffered survivors
    int cnt = 0;
    for (int p = 256; p < KTP; p += 4) {
        float s[8];
        score8(s, tA, tB, p, mx, my, mz);
        const int jb = 2*p;
#pragma unroll
        for (int u = 0; u < 8; u++) {
            int j = jb + u;
            bool keep = (s[u] > thr0) & (j != q) & (cnt < TCAP);
            if (keep) g_buf[(size_t)cnt * NP + q] = packSI(s[u], j);
            cnt += keep ? 1 : 0;
        }
    }
    for (int m = 0; m < cnt; m++) merge21(ss, scoreOf(g_buf[(size_t)m * NP + q]));

    if (cnt >= TCAP) {   // overflow guard (P~0): exact rescan of [0,2048)
#pragma unroll
        for (int t = 0; t < 21; t++) ss[t] = NEG;
        for (int p = 0; p < KTP; p += 4) {
            float s[8];
            score8(s, tA, tB, p, mx, my, mz);
#pragma unroll
            for (int u = 0; u < 8; u++) {
                float sv = (2*p + u != q) ? s[u] : NEG;
                merge21(ss, sv);
            }
        }
    }
    g_thr1[q] = ss[0];
}

// ---- knn filter: candidate-sliced full scan; private sub-buffers, no atomics ----
__global__ void knn_filter_kernel() {
    __shared__ double2 tA[KTP];
    __shared__ double2 tB[KTP];
    const int q = blockIdx.x * blockDim.x + threadIdx.x;
    const int slice = blockIdx.y;
    const int pb0 = slice * KTP;
    const float4 me = g_cand[q];
    const unsigned long long mx = bcast2(me.x), my = bcast2(me.y), mz = bcast2(me.z);
    const float thr1 = g_thr1[q];

    for (int l = threadIdx.x; l < KTP; l += blockDim.x) {
        tA[l] = ((const double2*)g_A)[pb0 + l];
        tB[l] = ((const double2*)g_B)[pb0 + l];
    }
    __syncthreads();

    unsigned long long* myb = &g_buf[((size_t)slice * SUBCAP) * NP + q];
    int cnt = 0;
    const int jb0 = 2*pb0;
    for (int p = 0; p < KTP; p += 4) {
        float s[8];
        score8(s, tA, tB, p, mx, my, mz);
        const int jb = jb0 + 2*p;
#pragma unroll
        for (int u = 0; u < 8; u++) {
            int j = jb + u;
            bool keep = (s[u] > thr1) & (j != q) & (cnt < SUBCAP);
            if (keep) myb[(size_t)cnt * NP] = packSI(s[u], j);   // @P STG, no branch
            cnt += keep ? 1 : 0;
        }
    }
    g_cntS[slice * NP + q] = cnt;
}

// ---- knn final: exact top-20 from per-slice survivor buffers ----
// Buffers are in ascending candidate-index order (slices partition index space
// in order, scans are in order) -> tie-break by lowest index matches lax.top_k.
__global__ void knn_final_kernel() {
    const int q = blockIdx.x * blockDim.x + threadIdx.x;
    const float NEG = -3.0e38f;

    float tt[21];
#pragma unroll
    for (int t = 0; t < 21; t++) tt[t] = NEG;
    bool ovf = false;
    for (int sl = 0; sl < NSLICE; sl++) {
        int c = g_cntS[sl * NP + q];
        ovf |= (c >= SUBCAP);
        for (int m = 0; m < c; m++)
            merge21(tt, scoreOf(g_buf[((size_t)sl * SUBCAP + m) * NP + q]));
    }
    float t21 = tt[0];

    int out = 0;
    for (int sl = 0; sl < NSLICE && out < KK; sl++) {           // strictly above 21st
        int c = g_cntS[sl * NP + q];
        for (int m = 0; m < c && out < KK; m++) {
            unsigned long long e = g_buf[((size_t)sl * SUBCAP + m) * NP + q];
            if (scoreOf(e) > t21) g_knn[q*KK + (out++)] = (int)(e & 0xffffffffu);
        }
    }
    for (int sl = 0; sl < NSLICE && out < KK; sl++) {           // ties, ascending index
        int c = g_cntS[sl * NP + q];
        for (int m = 0; m < c && out < KK; m++) {
            unsigned long long e = g_buf[((size_t)sl * SUBCAP + m) * NP + q];
            if (scoreOf(e) == t21) g_knn[q*KK + (out++)] = (int)(e & 0xffffffffu);
        }
    }

    if (out < KK || ovf) {   // P~0 exact brute-force fallback for this query
        const float4 me = g_cand[q];
        float ss[21];
#pragma unroll
        for (int t = 0; t < 21; t++) ss[t] = NEG;
        for (int j = 0; j < NP; j++) {
            float4 c = g_cand[j];
            float sv = fmaf(me.x, c.x, fmaf(me.y, c.y, fmaf(me.z, c.z, -c.w)));
            merge21(ss, (j != q) ? sv : NEG);
        }
        float b21 = ss[0];
        out = 0;
        for (int j = 0; j < NP && out < KK; j++) {
            if (j == q) continue;
            float4 c = g_cand[j];
            float sv = fmaf(me.x, c.x, fmaf(me.y, c.y, fmaf(me.z, c.z, -c.w)));
            if (sv > b21) g_knn[q*KK + (out++)] = j;
        }
        for (int j = 0; j < NP && out < KK; j++) {
            if (j == q) continue;
            float4 c = g_cand[j];
            float sv = fmaf(me.x, c.x, fmaf(me.y, c.y, fmaf(me.z, c.z, -c.w)));
            if (sv == b21) g_knn[q*KK + (out++)] = j;
        }
    }
}

// ---- SGEMM: AB[16384,512] = X[16384,128] @ W2[128,512]  (+bias on cols<256) ----
// Inner product via packed fma.rn.f32x2: 32 FFMA2 per k-step instead of 64 FFMA.
__global__ void gemm_kernel(const float* __restrict__ X, const float* __restrict__ bias) {
    __shared__ __align__(16) float As[8][128];
    __shared__ __align__(16) float Bs[8][128];
    const int tid = threadIdx.x;
    const int m0 = blockIdx.y * 128;
    const int n0 = blockIdx.x * 128;
    const int tx = tid & 15;
    const int ty = tid >> 4;
    const int lam = tid >> 1;
    const int lak = (tid & 1) * 4;
    const int lbr = tid >> 5;
    const int lbc = (tid & 31) * 4;

    unsigned long long acc[8][4];
#pragma unroll
    for (int i = 0; i < 8; i++)
#pragma unroll
        for (int j = 0; j < 4; j++) acc[i][j] = 0ull;   // {0.0f, 0.0f}

    for (int kb = 0; kb < CIN; kb += 8) {
        float4 av = *(const float4*)&X[(size_t)(m0 + lam)*CIN + kb + lak];
        float4 bv = *(const float4*)&g_W2[(kb + lbr)*WCOLS + n0 + lbc];
        __syncthreads();
        As[lak+0][lam] = av.x;
        As[lak+1][lam] = av.y;
        As[lak+2][lam] = av.z;
        As[lak+3][lam] = av.w;
        *(float4*)&Bs[lbr][lbc] = bv;
        __syncthreads();
#pragma unroll
        for (int k = 0; k < 8; k++) {
            float a[8];
            *(float4*)&a[0] = *(const float4*)&As[k][ty*8];
            *(float4*)&a[4] = *(const float4*)&As[k][ty*8 + 4];
            unsigned long long b2[4];
            const unsigned long long* bp = (const unsigned long long*)&Bs[k][tx*8];
            b2[0] = bp[0]; b2[1] = bp[1]; b2[2] = bp[2]; b2[3] = bp[3];
#pragma unroll
            for (int i = 0; i < 8; i++) {
                unsigned long long a2 = bcast2(a[i]);
#pragma unroll
                for (int j = 0; j < 4; j++)
                    acc[i][j] = ffma2(a2, b2[j], acc[i][j]);
            }
        }
    }
    const bool addb = (n0 < COUT);
#pragma unroll
    for (int i = 0; i < 8; i++) {
        int row = m0 + ty*8 + i;
        float r[8];
#pragma unroll
        for (int j = 0; j < 4; j++) unpack2(acc[i][j], r[2*j], r[2*j+1]);
#pragma unroll
        for (int j = 0; j < 8; j += 4) {
            int col = n0 + tx*8 + j;
            float4 v;
            v.x = r[j+0] + (addb ? bias[col+0] : 0.0f);
            v.y = r[j+1] + (addb ? bias[col+1] : 0.0f);
            v.z = r[j+2] + (addb ? bias[col+2] : 0.0f);
            v.w = r[j+3] + (addb ? bias[col+3] : 0.0f);
            *(float4*)&g_AB[(size_t)row*WCOLS + col] = v;
        }
    }
}

// ---- fused edge pass: per (i,c) extreme over neighbors + channel sum/sumsq ----
__global__ void edge_kernel(const float* __restrict__ gamma) {
    const int c  = threadIdx.x;
    const int i0 = blockIdx.x * QPB;
    const bool useMax = (gamma[c] >= 0.0f);
    float psum = 0.0f, psumsq = 0.0f;
    for (int g = 0; g < QPB; g++) {
        const int i = i0 + g;
        const float a = g_AB[(size_t)i*WCOLS + c];
        float best = useMax ? -3.0e38f : 3.0e38f;
#pragma unroll
        for (int k = 0; k < KK; k++) {
            int j = g_knn[i*KK + k];
            float h = a + g_AB[(size_t)j*WCOLS + COUT + c];
            psum += h;
            psumsq = fmaf(h, h, psumsq);
            best = useMax ? fmaxf(best, h) : fminf(best, h);
        }
        g_sel[(size_t)i*COUT + c] = best;
    }
    atomicAdd(&g_sumD[c], (double)psum);
    atomicAdd(&g_sumsqD[c], (double)psumsq);
}

// ---- BN stats -> per-channel scale/shift ----
__global__ void finalize_kernel(const float* __restrict__ gamma, const float* __restrict__ beta) {
    int c = threadIdx.x;
    const double inv = 1.0 / (double)(NP * KK);
    double m  = g_sumD[c] * inv;
    double v  = g_sumsqD[c] * inv - m*m;
    float sc = gamma[c] * rsqrtf((float)v + 1e-5f);
    g_scale[c] = sc;
    g_shift[c] = beta[c] - (float)m * sc;
}

// ---- epilogue: normalize selected extreme + LeakyReLU ----
__global__ void out_kernel(float* __restrict__ out) {
    int t = blockIdx.x * blockDim.x + threadIdx.x;
    int c = t & (COUT - 1);
    float h = fmaf(g_sel[t], g_scale[c], g_shift[c]);
    out[t] = (h >= 0.0f) ? h : 0.2f*h;
}

extern "C" void kernel_launch(void* const* d_in, const int* in_sizes, int n_in,
                              void* d_out, int out_size) {
    const float* pos   = (const float*)d_in[0];
    const float* x     = (const float*)d_in[1];
    const float* W     = (const float*)d_in[2];
    const float* b     = (const float*)d_in[3];
    const float* gamma = (const float*)d_in[4];
    const float* beta  = (const float*)d_in[5];
    float* out = (float*)d_out;

    prep_kernel<<<256, 256>>>(pos, W);                         // 0
    knn_thresh_kernel<<<NP / 256, 256>>>();                    // 1
    gemm_kernel<<<dim3(WCOLS / 128, NP / 128), 256>>>(x, b);   // 2
    knn_filter_kernel<<<dim3(NP / 256, NSLICE), 256>>>();      // 3 (ncu slot)
    knn_final_kernel<<<NP / 256, 256>>>();                     // 4
    edge_kernel<<<NP / QPB, 256>>>(gamma);                     // 5
    finalize_kernel<<<1, COUT>>>(gamma, beta);                 // 6
    out_kernel<<<(NP * COUT) / 256, 256>>>(out);               // 7
}

// round 7
// speedup vs baseline: 1.4998x; 1.0172x over previous
#include <cuda_runtime.h>

#define NP     16384
#define CIN    128
#define COUT   256
#define KK     20
#define WCOLS  512
#define QPB    8
#define NSLICE 8         /* candidate slices for the filter kernel */
#define KTP    1024      /* pairs per slice tile -> 2048 candidates, 32KB smem */
#define SUBCAP 192       /* survivor entries per (query, slice) */

// ---- scratch (no allocations allowed: __device__ globals) ----
__device__ float4 g_cand[NP];          // {x,y,z,|p|^2/2}
__device__ float4 g_A[NP/2];           // pair-SoA {x0,x1,y0,y1}
__device__ float4 g_B[NP/2];           // pair-SoA {z0,z1,-w0,-w1}
__device__ float  g_thr1[NP];          // lower bound on global 21st-best score
__device__ int    g_cntS[NSLICE * NP]; // survivor count per (slice, query)
__device__ int    g_bufI[(size_t)(NSLICE*SUBCAP) * NP]; // survivor indices, lane-interleaved
__device__ int    g_knn[NP * KK];
__device__ float  g_W2[CIN * WCOLS];
__device__ float  g_AB[(size_t)NP * WCOLS];   // [:,0:256)=A(+bias), [:,256:512)=B
__device__ float  g_sel[(size_t)NP * COUT];
__device__ double g_sumD[COUT];
__device__ double g_sumsqD[COUT];
__device__ float  g_scale[COUT];
__device__ float  g_shift[COUT];

// ---------- packed f32x2 helpers ----------
__device__ __forceinline__ unsigned long long ffma2(unsigned long long a,
                                                    unsigned long long b,
                                                    unsigned long long c) {
    unsigned long long d;
    asm("fma.rn.f32x2 %0, %1, %2, %3;" : "=l"(d) : "l"(a), "l"(b), "l"(c));
    return d;
}
__device__ __forceinline__ unsigned long long bcast2(float x) {
    unsigned long long r;
    asm("mov.b64 %0, {%1, %1};" : "=l"(r) : "f"(x));
    return r;
}
__device__ __forceinline__ void unpack2(unsigned long long v, float& lo, float& hi) {
    asm("mov.b64 {%0, %1}, %2;" : "=f"(lo), "=f"(hi) : "l"(v));
}
__device__ __forceinline__ unsigned long long d_as_ll(double d) {
    return __double_as_longlong(d);
}

// sorted-ascending merge-inserts (drop current min); branchless
__device__ __forceinline__ void merge21(float (&ss)[21], float sv) {
#pragma unroll
    for (int t = 0; t < 20; t++) ss[t] = fmaxf(ss[t], fminf(sv, ss[t+1]));
    ss[20] = fmaxf(ss[20], sv);
}
__device__ __forceinline__ void merge22(float (&ss)[22], float sv) {
#pragma unroll
    for (int t = 0; t < 21; t++) ss[t] = fmaxf(ss[t], fminf(sv, ss[t+1]));
    ss[21] = fmaxf(ss[21], sv);
}

// 8 scores (4 packed pairs) from smem tiles
__device__ __forceinline__ void score8(float* s, const double2* tA, const double2* tB, int p,
                                       unsigned long long mx, unsigned long long my,
                                       unsigned long long mz) {
#pragma unroll
    for (int w = 0; w < 4; w++) {
        double2 a = tA[p + w];
        double2 b = tB[p + w];
        unsigned long long t0 = ffma2(mz, d_as_ll(b.x), d_as_ll(b.y));  // z*mz - w
        t0 = ffma2(my, d_as_ll(a.y), t0);
        t0 = ffma2(mx, d_as_ll(a.x), t0);
        unpack2(t0, s[2*w], s[2*w+1]);
    }
}

// scalar score, identical rounding to the packed path
__device__ __forceinline__ float scoreQ(const float4& me, const float4& c) {
    return fmaf(me.x, c.x, fmaf(me.y, c.y, fmaf(me.z, c.z, -c.w)));
}

// ---- prep: candidates (AoS + pair-SoA), W rearrange, stat zeroing ----
__global__ void prep_kernel(const float* __restrict__ pos, const float* __restrict__ W) {
    int t = blockIdx.x * blockDim.x + threadIdx.x;
    if (t < NP) {
        float x = pos[3*t+0], y = pos[3*t+1], z = pos[3*t+2];
        g_cand[t] = make_float4(x, y, z, 0.5f*(x*x + y*y + z*z));
    }
    if (t < NP/2) {
        int j0 = 2*t, j1 = 2*t + 1;
        float x0 = pos[3*j0+0], y0 = pos[3*j0+1], z0 = pos[3*j0+2];
        float x1 = pos[3*j1+0], y1 = pos[3*j1+1], z1 = pos[3*j1+2];
        float w0 = 0.5f*(x0*x0 + y0*y0 + z0*z0);
        float w1 = 0.5f*(x1*x1 + y1*y1 + z1*z1);
        g_A[t] = make_float4(x0, x1, y0, y1);
        g_B[t] = make_float4(z0, z1, -w0, -w1);
    }
    if (t < CIN * WCOLS) {
        int kk = t >> 9;
        int c  = t & 511;
        g_W2[t] = (c < COUT) ? W[kk*COUT + c] : W[(kk + CIN)*COUT + (c - COUT)];
    }
    if (t < COUT) { g_sumD[t] = 0.0; g_sumsqD[t] = 0.0; }
}

// ---- knn threshold: cheap valid lower bound on the global 21st-best score ----
// Over candidates [0,2048): compute 64 chunk-maxes (32 cands each), take the
// 22nd largest. Subset order statistic <= superset order statistic, and the
// extra (22nd) slot absorbs the self-score, so thr1 <= global 21st (excl self).
__global__ void knn_thresh_kernel() {
    __shared__ double2 tA[KTP];
    __shared__ double2 tB[KTP];
    const int q = blockIdx.x * blockDim.x + threadIdx.x;
    const float4 me = g_cand[q];
    const unsigned long long mx = bcast2(me.x), my = bcast2(me.y), mz = bcast2(me.z);
    const float NEG = -3.0e38f;

    for (int l = threadIdx.x; l < KTP; l += blockDim.x) {
        tA[l] = ((const double2*)g_A)[l];
        tB[l] = ((const double2*)g_B)[l];
    }
    __syncthreads();

    float ss[22];
#pragma unroll
    for (int t = 0; t < 22; t++) ss[t] = NEG;

    for (int p = 0; p < KTP; p += 16) {        // 32 candidates per chunk
        float cm = NEG;
#pragma unroll
        for (int o = 0; o < 4; o++) {
            float s[8];
            score8(s, tA, tB, p + 4*o, mx, my, mz);
#pragma unroll
            for (int u = 0; u < 8; u++) cm = fmaxf(cm, s[u]);
        }
        merge22(ss, cm);
    }
    g_thr1[q] = ss[0];
}

// ---- knn filter: candidate-sliced full scan; private sub-buffers, no atomics ----
// Stores 4-byte indices only; self-survivor kept (removed in final).
__global__ void knn_filter_kernel() {
    __shared__ double2 tA[KTP];
    __shared__ double2 tB[KTP];
    const int q = blockIdx.x * blockDim.x + threadIdx.x;
    const int slice = blockIdx.y;
    const int pb0 = slice * KTP;
    const float4 me = g_cand[q];
    const unsigned long long mx = bcast2(me.x), my = bcast2(me.y), mz = bcast2(me.z);
    const float thr1 = g_thr1[q];

    for (int l = threadIdx.x; l < KTP; l += blockDim.x) {
        tA[l] = ((const double2*)g_A)[pb0 + l];
        tB[l] = ((const double2*)g_B)[pb0 + l];
    }
    __syncthreads();

    const int base = (slice * SUBCAP) * NP + q;     // 32-bit offsets throughout
    int cnt = 0;
    const int jb0 = 2*pb0;
    for (int p = 0; p < KTP; p += 4) {
        float s[8];
        score8(s, tA, tB, p, mx, my, mz);
        const int jb = jb0 + 2*p;
#pragma unroll
        for (int u = 0; u < 8; u++) {
            bool keep = (s[u] > thr1);
            if (keep & (cnt < SUBCAP)) g_bufI[base + cnt * NP] = jb + u;  // @P STG.32
            cnt += keep ? 1 : 0;
        }
    }
    g_cntS[slice * NP + q] = cnt;   // may exceed SUBCAP -> overflow flag for final
}

// ---- knn final: exact top-20 from per-slice survivor buffers (scores recomputed) ----
// Buffers are ascending-index -> tie-break by lowest index matches lax.top_k.
__global__ void knn_final_kernel() {
    const int q = blockIdx.x * blockDim.x + threadIdx.x;
    const float NEG = -3.0e38f;
    const float4 me = g_cand[q];

    float tt[21];
#pragma unroll
    for (int t = 0; t < 21; t++) tt[t] = NEG;
    bool ovf = false;
    for (int sl = 0; sl < NSLICE; sl++) {
        int c = g_cntS[sl * NP + q];
        ovf |= (c > SUBCAP);
        if (c > SUBCAP) c = SUBCAP;
        const int base = (sl * SUBCAP) * NP + q;
        for (int m = 0; m < c; m++) {
            int j = g_bufI[base + m * NP];
            float sv = (j != q) ? scoreQ(me, g_cand[j]) : NEG;
            merge21(tt, sv);
        }
    }
    const float t21 = tt[0];

    int out = 0;
    for (int sl = 0; sl < NSLICE && out < KK; sl++) {           // strictly above 21st
        int c = g_cntS[sl * NP + q];
        if (c > SUBCAP) c = SUBCAP;
        const int base = (sl * SUBCAP) * NP + q;
        for (int m = 0; m < c && out < KK; m++) {
            int j = g_bufI[base + m * NP];
            if (j != q && scoreQ(me, g_cand[j]) > t21) g_knn[q*KK + (out++)] = j;
        }
    }
    for (int sl = 0; sl < NSLICE && out < KK; sl++) {           // ties, ascending index
        int c = g_cntS[sl * NP + q];
        if (c > SUBCAP) c = SUBCAP;
        const int base = (sl * SUBCAP) * NP + q;
        for (int m = 0; m < c && out < KK; m++) {
            int j = g_bufI[base + m * NP];
            if (j != q && scoreQ(me, g_cand[j]) == t21) g_knn[q*KK + (out++)] = j;
        }
    }

    if (out < KK || ovf) {   // P~0 exact brute-force fallback for this query
        float ss[21];
#pragma unroll
        for (int t = 0; t < 21; t++) ss[t] = NEG;
        for (int j = 0; j < NP; j++)
            merge21(ss, (j != q) ? scoreQ(me, g_cand[j]) : NEG);
        float b21 = ss[0];
        out = 0;
        for (int j = 0; j < NP && out < KK; j++)
            if (j != q && scoreQ(me, g_cand[j]) > b21) g_knn[q*KK + (out++)] = j;
        for (int j = 0; j < NP && out < KK; j++)
            if (j != q && scoreQ(me, g_cand[j]) == b21) g_knn[q*KK + (out++)] = j;
    }
}

// ---- SGEMM: AB[16384,512] = X[16384,128] @ W2[128,512]  (+bias on cols<256) ----
// Inner product via packed fma.rn.f32x2: 32 FFMA2 per k-step instead of 64 FFMA.
__global__ void gemm_kernel(const float* __restrict__ X, const float* __restrict__ bias) {
    __shared__ __align__(16) float As[8][128];
    __shared__ __align__(16) float Bs[8][128];
    const int tid = threadIdx.x;
    const int m0 = blockIdx.y * 128;
    const int n0 = blockIdx.x * 128;
    const int tx = tid & 15;
    const int ty = tid >> 4;
    const int lam = tid >> 1;
    const int lak = (tid & 1) * 4;
    const int lbr = tid >> 5;
    const int lbc = (tid & 31) * 4;

    unsigned long long acc[8][4];
#pragma unroll
    for (int i = 0; i < 8; i++)
#pragma unroll
        for (int j = 0; j < 4; j++) acc[i][j] = 0ull;

    for (int kb = 0; kb < CIN; kb += 8) {
        float4 av = *(const float4*)&X[(size_t)(m0 + lam)*CIN + kb + lak];
        float4 bv = *(const float4*)&g_W2[(kb + lbr)*WCOLS + n0 + lbc];
        __syncthreads();
        As[lak+0][lam] = av.x;
        As[lak+1][lam] = av.y;
        As[lak+2][lam] = av.z;
        As[lak+3][lam] = av.w;
        *(float4*)&Bs[lbr][lbc] = bv;
        __syncthreads();
#pragma unroll
        for (int k = 0; k < 8; k++) {
            float a[8];
            *(float4*)&a[0] = *(const float4*)&As[k][ty*8];
            *(float4*)&a[4] = *(const float4*)&As[k][ty*8 + 4];
            unsigned long long b2[4];
            const unsigned long long* bp = (const unsigned long long*)&Bs[k][tx*8];
            b2[0] = bp[0]; b2[1] = bp[1]; b2[2] = bp[2]; b2[3] = bp[3];
#pragma unroll
            for (int i = 0; i < 8; i++) {
                unsigned long long a2 = bcast2(a[i]);
#pragma unroll
                for (int j = 0; j < 4; j++)
                    acc[i][j] = ffma2(a2, b2[j], acc[i][j]);
            }
        }
    }
    const bool addb = (n0 < COUT);
#pragma unroll
    for (int i = 0; i < 8; i++) {
        int row = m0 + ty*8 + i;
        float r[8];
#pragma unroll
        for (int j = 0; j < 4; j++) unpack2(acc[i][j], r[2*j], r[2*j+1]);
#pragma unroll
        for (int j = 0; j < 8; j += 4) {
            int col = n0 + tx*8 + j;
            float4 v;
            v.x = r[j+0] + (addb ? bias[col+0] : 0.0f);
            v.y = r[j+1] + (addb ? bias[col+1] : 0.0f);
            v.z = r[j+2] + (addb ? bias[col+2] : 0.0f);
            v.w = r[j+3] + (addb ? bias[col+3] : 0.0f);
            *(float4*)&g_AB[(size_t)row*WCOLS + col] = v;
        }
    }
}

// ---- fused edge pass: 2 channels/thread, per (i,c) extreme + channel sum/sumsq ----
__global__ void edge_kernel(const float* __restrict__ gamma) {
    const int c2 = threadIdx.x;            // 0..127 -> channels 2*c2, 2*c2+1
    const int c0 = 2*c2;
    const int i0 = blockIdx.x * QPB;
    const bool uM0 = (gamma[c0]   >= 0.0f);
    const bool uM1 = (gamma[c0+1] >= 0.0f);
    float ps0 = 0.f, ps1 = 0.f, pq0 = 0.f, pq1 = 0.f;
    for (int g = 0; g < QPB; g++) {
        const int i = i0 + g;
        float2 a = *(const float2*)&g_AB[(size_t)i*WCOLS + c0];
        float b0 = uM0 ? -3.0e38f : 3.0e38f;
        float b1 = uM1 ? -3.0e38f : 3.0e38f;
#pragma unroll
        for (int k = 0; k < KK; k++) {
            int j = g_knn[i*KK + k];
            float2 bv = *(const float2*)&g_AB[(size_t)j*WCOLS + COUT + c0];
            float h0 = a.x + bv.x;
            float h1 = a.y + bv.y;
            ps0 += h0; pq0 = fmaf(h0, h0, pq0);
            ps1 += h1; pq1 = fmaf(h1, h1, pq1);
            b0 = uM0 ? fmaxf(b0, h0) : fminf(b0, h0);
            b1 = uM1 ? fmaxf(b1, h1) : fminf(b1, h1);
        }
        *(float2*)&g_sel[(size_t)i*COUT + c0] = make_float2(b0, b1);
    }
    atomicAdd(&g_sumD[c0],     (double)ps0);
    atomicAdd(&g_sumD[c0+1],   (double)ps1);
    atomicAdd(&g_sumsqD[c0],   (double)pq0);
    atomicAdd(&g_sumsqD[c0+1], (double)pq1);
}

// ---- BN stats -> per-channel scale/shift ----
__global__ void finalize_kernel(const float* __restrict__ gamma, const float* __restrict__ beta) {
    int c = threadIdx.x;
    const double inv = 1.0 / (double)(NP * KK);
    double m  = g_sumD[c] * inv;
    double v  = g_sumsqD[c] * inv - m*m;
    float sc = gamma[c] * rsqrtf((float)v + 1e-5f);
    g_scale[c] = sc;
    g_shift[c] = beta[c] - (float)m * sc;
}

// ---- epilogue: normalize selected extreme + LeakyReLU ----
__global__ void out_kernel(float* __restrict__ out) {
    int t = blockIdx.x * blockDim.x + threadIdx.x;
    int c = t & (COUT - 1);
    float h = fmaf(g_sel[t], g_scale[c], g_shift[c]);
    out[t] = (h >= 0.0f) ? h : 0.2f*h;
}

extern "C" void kernel_launch(void* const* d_in, const int* in_sizes, int n_in,
                              void* d_out, int out_size) {
    const float* pos   = (const float*)d_in[0];
    const float* x     = (const float*)d_in[1];
    const float* W     = (const float*)d_in[2];
    const float* b     = (const float*)d_in[3];
    const float* gamma = (const float*)d_in[4];
    const float* beta  = (const float*)d_in[5];
    float* out = (float*)d_out;

    prep_kernel<<<256, 256>>>(pos, W);                         // 0
    knn_thresh_kernel<<<NP / 128, 128>>>();                    // 1
    knn_filter_kernel<<<dim3(NP / 256, NSLICE), 256>>>();      // 2
    knn_final_kernel<<<NP / 128, 128>>>();                     // 3 (ncu slot)
    gemm_kernel<<<dim3(WCOLS / 128, NP / 128), 256>>>(x, b);   // 4
    edge_kernel<<<NP / QPB, 128>>>(gamma);                     // 5
    finalize_kernel<<<1, COUT>>>(gamma, beta);                 // 6
    out_kernel<<<(NP * COUT) / 256, 256>>>(out);               // 7
}

// round 8
// speedup vs baseline: 1.6923x; 1.1284x over previous
#include <cuda_runtime.h>

#define NP     16384
#define CIN    128
#define COUT   256
#define KK     20
#define WCOLS  512
#define QPB    8
#define NSLICE 8         /* candidate slices for the filter kernel */
#define KTP    1024      /* pairs per slice tile -> 2048 candidates, 32KB smem */
#define SUBCAP 128       /* survivor entries per (query, slice) */

// ---- scratch (no allocations allowed: __device__ globals) ----
__device__ float4 g_cand[NP];          // {x,y,z,|p|^2/2}
__device__ float4 g_A[NP/2];           // pair-SoA {x0,x1,y0,y1}
__device__ float4 g_B[NP/2];           // pair-SoA {z0,z1,-w0,-w1}
__device__ float  g_thr1[NP];          // lower bound on global 21st-best score
__device__ int    g_cntS[NSLICE * NP]; // survivor count per (slice, query)
__device__ unsigned long long g_buf[(size_t)(NSLICE*SUBCAP) * NP]; // (score<<32|idx), lane-interleaved
__device__ int    g_knn[NP * KK];
__device__ float  g_W2[CIN * WCOLS];
__device__ float  g_AB[(size_t)NP * WCOLS];   // [:,0:256)=A(+bias), [:,256:512)=B
__device__ float  g_sel[(size_t)NP * COUT];
__device__ double g_sumD[COUT];
__device__ double g_sumsqD[COUT];
__device__ float  g_scale[COUT];
__device__ float  g_shift[COUT];

// ---------- packed f32x2 helpers ----------
__device__ __forceinline__ unsigned long long ffma2(unsigned long long a,
                                                    unsigned long long b,
                                                    unsigned long long c) {
    unsigned long long d;
    asm("fma.rn.f32x2 %0, %1, %2, %3;" : "=l"(d) : "l"(a), "l"(b), "l"(c));
    return d;
}
__device__ __forceinline__ unsigned long long bcast2(float x) {
    unsigned long long r;
    asm("mov.b64 %0, {%1, %1};" : "=l"(r) : "f"(x));
    return r;
}
__device__ __forceinline__ void unpack2(unsigned long long v, float& lo, float& hi) {
    asm("mov.b64 {%0, %1}, %2;" : "=f"(lo), "=f"(hi) : "l"(v));
}
__device__ __forceinline__ unsigned long long d_as_ll(double d) {
    return __double_as_longlong(d);
}

// sorted-ascending merge-inserts (drop current min); branchless
__device__ __forceinline__ void merge21(float (&ss)[21], float sv) {
#pragma unroll
    for (int t = 0; t < 20; t++) ss[t] = fmaxf(ss[t], fminf(sv, ss[t+1]));
    ss[20] = fmaxf(ss[20], sv);
}
__device__ __forceinline__ void merge22(float (&ss)[22], float sv) {
#pragma unroll
    for (int t = 0; t < 21; t++) ss[t] = fmaxf(ss[t], fminf(sv, ss[t+1]));
    ss[21] = fmaxf(ss[21], sv);
}

// 8 scores (4 packed pairs) from smem tiles
__device__ __forceinline__ void score8(float* s, const double2* tA, const double2* tB, int p,
                                       unsigned long long mx, unsigned long long my,
                                       unsigned long long mz) {
#pragma unroll
    for (int w = 0; w < 4; w++) {
        double2 a = tA[p + w];
        double2 b = tB[p + w];
        unsigned long long t0 = ffma2(mz, d_as_ll(b.x), d_as_ll(b.y));  // z*mz - w
        t0 = ffma2(my, d_as_ll(a.y), t0);
        t0 = ffma2(mx, d_as_ll(a.x), t0);
        unpack2(t0, s[2*w], s[2*w+1]);
    }
}

// scalar score, identical rounding to the packed path
__device__ __forceinline__ float scoreQ(const float4& me, const float4& c) {
    return fmaf(me.x, c.x, fmaf(me.y, c.y, fmaf(me.z, c.z, -c.w)));
}

__device__ __forceinline__ unsigned long long packSI(float s, int j) {
    return ((unsigned long long)__float_as_uint(s) << 32) | (unsigned)j;
}
__device__ __forceinline__ float scoreOf(unsigned long long e) {
    return __uint_as_float((unsigned)(e >> 32));
}
__device__ __forceinline__ int idxOf(unsigned long long e) {
    return (int)(e & 0xffffffffu);
}

// ---- prep: candidates (AoS + pair-SoA), W rearrange, stat zeroing ----
__global__ void prep_kernel(const float* __restrict__ pos, const float* __restrict__ W) {
    int t = blockIdx.x * blockDim.x + threadIdx.x;
    if (t < NP) {
        float x = pos[3*t+0], y = pos[3*t+1], z = pos[3*t+2];
        g_cand[t] = make_float4(x, y, z, 0.5f*(x*x + y*y + z*z));
    }
    if (t < NP/2) {
        int j0 = 2*t, j1 = 2*t + 1;
        float x0 = pos[3*j0+0], y0 = pos[3*j0+1], z0 = pos[3*j0+2];
        float x1 = pos[3*j1+0], y1 = pos[3*j1+1], z1 = pos[3*j1+2];
        float w0 = 0.5f*(x0*x0 + y0*y0 + z0*z0);
        float w1 = 0.5f*(x1*x1 + y1*y1 + z1*z1);
        g_A[t] = make_float4(x0, x1, y0, y1);
        g_B[t] = make_float4(z0, z1, -w0, -w1);
    }
    if (t < CIN * WCOLS) {
        int kk = t >> 9;
        int c  = t & 511;
        g_W2[t] = (c < COUT) ? W[kk*COUT + c] : W[(kk + CIN)*COUT + (c - COUT)];
    }
    if (t < COUT) { g_sumD[t] = 0.0; g_sumsqD[t] = 0.0; }
}

// ---- knn threshold: cheap valid lower bound on the global 21st-best score ----
// Over candidates [0,2048): compute 64 chunk-maxes (32 cands each), take the
// 22nd largest. Subset order statistic <= superset order statistic, and the
// extra (22nd) slot absorbs the self-score, so thr1 <= global 21st (excl self).
__global__ void knn_thresh_kernel() {
    __shared__ double2 tA[KTP];
    __shared__ double2 tB[KTP];
    const int q = blockIdx.x * blockDim.x + threadIdx.x;
    const float4 me = g_cand[q];
    const unsigned long long mx = bcast2(me.x), my = bcast2(me.y), mz = bcast2(me.z);
    const float NEG = -3.0e38f;

    for (int l = threadIdx.x; l < KTP; l += blockDim.x) {
        tA[l] = ((const double2*)g_A)[l];
        tB[l] = ((const double2*)g_B)[l];
    }
    __syncthreads();

    float ss[22];
#pragma unroll
    for (int t = 0; t < 22; t++) ss[t] = NEG;

    for (int p = 0; p < KTP; p += 16) {        // 32 candidates per chunk
        float cm = NEG;
#pragma unroll
        for (int o = 0; o < 4; o++) {
            float s[8];
            score8(s, tA, tB, p + 4*o, mx, my, mz);
#pragma unroll
            for (int u = 0; u < 8; u++) cm = fmaxf(cm, s[u]);
        }
        merge22(ss, cm);
    }
    g_thr1[q] = ss[0];
}

// ---- knn filter: candidate-sliced full scan; private sub-buffers, no atomics ----
// Stores packed (score, idx); self survives (it is always the strict max).
__global__ void knn_filter_kernel() {
    __shared__ double2 tA[KTP];
    __shared__ double2 tB[KTP];
    const int q = blockIdx.x * blockDim.x + threadIdx.x;
    const int slice = blockIdx.y;
    const int pb0 = slice * KTP;
    const float4 me = g_cand[q];
    const unsigned long long mx = bcast2(me.x), my = bcast2(me.y), mz = bcast2(me.z);
    const float thr1 = g_thr1[q];

    for (int l = threadIdx.x; l < KTP; l += blockDim.x) {
        tA[l] = ((const double2*)g_A)[pb0 + l];
        tB[l] = ((const double2*)g_B)[pb0 + l];
    }
    __syncthreads();

    unsigned long long* myb = &g_buf[(size_t)(slice * SUBCAP) * NP + q];
    int cnt = 0;
    const int jb0 = 2*pb0;
    for (int p = 0; p < KTP; p += 4) {
        float s[8];
        score8(s, tA, tB, p, mx, my, mz);
        const int jb = jb0 + 2*p;
#pragma unroll
        for (int u = 0; u < 8; u++) {
            bool keep = (s[u] > thr1);
            if (keep & (cnt < SUBCAP)) myb[cnt * NP] = packSI(s[u], jb + u);  // @P STG.64
            cnt += keep ? 1 : 0;
        }
    }
    g_cntS[slice * NP + q] = cnt;   // may exceed SUBCAP -> overflow flag for final
}

// ---- knn final: exact top-20 from packed survivor buffers (coalesced streams) ----
// Self is the unique strict max score, so the 22nd-largest including self equals
// the 21st-largest excluding self: merge ALL survivors into a 22-list, no idx test.
// Buffers are ascending-index -> tie-break by lowest index matches lax.top_k.
__global__ void knn_final_kernel() {
    const int q = blockIdx.x * blockDim.x + threadIdx.x;
    const float NEG = -3.0e38f;

    float ss[22];
#pragma unroll
    for (int t = 0; t < 22; t++) ss[t] = NEG;
    bool ovf = false;
    for (int sl = 0; sl < NSLICE; sl++) {
        int c = g_cntS[sl * NP + q];
        ovf |= (c > SUBCAP);
        if (c > SUBCAP) c = SUBCAP;
        const unsigned long long* myb = &g_buf[(size_t)(sl * SUBCAP) * NP + q];
        int m = 0;
        for (; m + 4 <= c; m += 4) {                       // batched: MLP=4 hides L2
            unsigned long long e0 = myb[(m+0) * NP];
            unsigned long long e1 = myb[(m+1) * NP];
            unsigned long long e2 = myb[(m+2) * NP];
            unsigned long long e3 = myb[(m+3) * NP];
            merge22(ss, scoreOf(e0));
            merge22(ss, scoreOf(e1));
            merge22(ss, scoreOf(e2));
            merge22(ss, scoreOf(e3));
        }
        for (; m < c; m++) merge22(ss, scoreOf(myb[m * NP]));
    }
    const float t21 = ss[0];   // 21st best excluding self

    int out = 0;
    for (int sl = 0; sl < NSLICE && out < KK; sl++) {      // strictly above 21st
        int c = g_cntS[sl * NP + q];
        if (c > SUBCAP) c = SUBCAP;
        const unsigned long long* myb = &g_buf[(size_t)(sl * SUBCAP) * NP + q];
        for (int m = 0; m < c && out < KK; m++) {
            unsigned long long e = myb[m * NP];
            int j = idxOf(e);
            if (scoreOf(e) > t21 && j != q) g_knn[q*KK + (out++)] = j;
        }
    }
    for (int sl = 0; sl < NSLICE && out < KK; sl++) {      // ties, ascending index
        int c = g_cntS[sl * NP + q];
        if (c > SUBCAP) c = SUBCAP;
        const unsigned long long* myb = &g_buf[(size_t)(sl * SUBCAP) * NP + q];
        for (int m = 0; m < c && out < KK; m++) {
            unsigned long long e = myb[m * NP];
            int j = idxOf(e);
            if (scoreOf(e) == t21 && j != q) g_knn[q*KK + (out++)] = j;
        }
    }

    if (out < KK || ovf) {   // P~0 exact brute-force fallback for this query
        const float4 me = g_cand[q];
        float bs[21];
#pragma unroll
        for (int t = 0; t < 21; t++) bs[t] = NEG;
        for (int j = 0; j < NP; j++)
            merge21(bs, (j != q) ? scoreQ(me, g_cand[j]) : NEG);
        float b21 = bs[0];
        out = 0;
        for (int j = 0; j < NP && out < KK; j++)
            if (j != q && scoreQ(me, g_cand[j]) > b21) g_knn[q*KK + (out++)] = j;
        for (int j = 0; j < NP && out < KK; j++)
            if (j != q && scoreQ(me, g_cand[j]) == b21) g_knn[q*KK + (out++)] = j;
    }
}

// ---- SGEMM: AB[16384,512] = X[16384,128] @ W2[128,512]  (+bias on cols<256) ----
// Inner product via packed fma.rn.f32x2: 32 FFMA2 per k-step instead of 64 FFMA.
__global__ void gemm_kernel(const float* __restrict__ X, const float* __restrict__ bias) {
    __shared__ __align__(16) float As[8][128];
    __shared__ __align__(16) float Bs[8][128];
    const int tid = threadIdx.x;
    const int m0 = blockIdx.y * 128;
    const int n0 = blockIdx.x * 128;
    const int tx = tid & 15;
    const int ty = tid >> 4;
    const int lam = tid >> 1;
    const int lak = (tid & 1) * 4;
    const int lbr = tid >> 5;
    const int lbc = (tid & 31) * 4;

    unsigned long long acc[8][4];
#pragma unroll
    for (int i = 0; i < 8; i++)
#pragma unroll
        for (int j = 0; j < 4; j++) acc[i][j] = 0ull;

    for (int kb = 0; kb < CIN; kb += 8) {
        float4 av = *(const float4*)&X[(size_t)(m0 + lam)*CIN + kb + lak];
        float4 bv = *(const float4*)&g_W2[(kb + lbr)*WCOLS + n0 + lbc];
        __syncthreads();
        As[lak+0][lam] = av.x;
        As[lak+1][lam] = av.y;
        As[lak+2][lam] = av.z;
        As[lak+3][lam] = av.w;
        *(float4*)&Bs[lbr][lbc] = bv;
        __syncthreads();
#pragma unroll
        for (int k = 0; k < 8; k++) {
            float a[8];
            *(float4*)&a[0] = *(const float4*)&As[k][ty*8];
            *(float4*)&a[4] = *(const float4*)&As[k][ty*8 + 4];
            unsigned long long b2[4];
            const unsigned long long* bp = (const unsigned long long*)&Bs[k][tx*8];
            b2[0] = bp[0]; b2[1] = bp[1]; b2[2] = bp[2]; b2[3] = bp[3];
#pragma unroll
            for (int i = 0; i < 8; i++) {
                unsigned long long a2 = bcast2(a[i]);
#pragma unroll
                for (int j = 0; j < 4; j++)
                    acc[i][j] = ffma2(a2, b2[j], acc[i][j]);
            }
        }
    }
    const bool addb = (n0 < COUT);
#pragma unroll
    for (int i = 0; i < 8; i++) {
        int row = m0 + ty*8 + i;
        float r[8];
#pragma unroll
        for (int j = 0; j < 4; j++) unpack2(acc[i][j], r[2*j], r[2*j+1]);
#pragma unroll
        for (int j = 0; j < 8; j += 4) {
            int col = n0 + tx*8 + j;
            float4 v;
            v.x = r[j+0] + (addb ? bias[col+0] : 0.0f);
            v.y = r[j+1] + (addb ? bias[col+1] : 0.0f);
            v.z = r[j+2] + (addb ? bias[col+2] : 0.0f);
            v.w = r[j+3] + (addb ? bias[col+3] : 0.0f);
            *(float4*)&g_AB[(size_t)row*WCOLS + col] = v;
        }
    }
}

// ---- fused edge pass: 2 channels/thread, per (i,c) extreme + channel sum/sumsq ----
__global__ void edge_kernel(const float* __restrict__ gamma) {
    const int c2 = threadIdx.x;            // 0..127 -> channels 2*c2, 2*c2+1
    const int c0 = 2*c2;
    const int i0 = blockIdx.x * QPB;
    const bool uM0 = (gamma[c0]   >= 0.0f);
    const bool uM1 = (gamma[c0+1] >= 0.0f);
    float ps0 = 0.f, ps1 = 0.f, pq0 = 0.f, pq1 = 0.f;
    for (int g = 0; g < QPB; g++) {
        const int i = i0 + g;
        float2 a = *(const float2*)&g_AB[(size_t)i*WCOLS + c0];
        float b0 = uM0 ? -3.0e38f : 3.0e38f;
        float b1 = uM1 ? -3.0e38f : 3.0e38f;
#pragma unroll
        for (int k = 0; k < KK; k++) {
            int j = g_knn[i*KK + k];
            float2 bv = *(const float2*)&g_AB[(size_t)j*WCOLS + COUT + c0];
            float h0 = a.x + bv.x;
            float h1 = a.y + bv.y;
            ps0 += h0; pq0 = fmaf(h0, h0, pq0);
            ps1 += h1; pq1 = fmaf(h1, h1, pq1);
            b0 = uM0 ? fmaxf(b0, h0) : fminf(b0, h0);
            b1 = uM1 ? fmaxf(b1, h1) : fminf(b1, h1);
        }
        *(float2*)&g_sel[(size_t)i*COUT + c0] = make_float2(b0, b1);
    }
    atomicAdd(&g_sumD[c0],     (double)ps0);
    atomicAdd(&g_sumD[c0+1],   (double)ps1);
    atomicAdd(&g_sumsqD[c0],   (double)pq0);
    atomicAdd(&g_sumsqD[c0+1], (double)pq1);
}

// ---- BN stats -> per-channel scale/shift ----
__global__ void finalize_kernel(const float* __restrict__ gamma, const float* __restrict__ beta) {
    int c = threadIdx.x;
    const double inv = 1.0 / (double)(NP * KK);
    double m  = g_sumD[c] * inv;
    double v  = g_sumsqD[c] * inv - m*m;
    float sc = gamma[c] * rsqrtf((float)v + 1e-5f);
    g_scale[c] = sc;
    g_shift[c] = beta[c] - (float)m * sc;
}

// ---- epilogue: normalize selected extreme + LeakyReLU ----
__global__ void out_kernel(float* __restrict__ out) {
    int t = blockIdx.x * blockDim.x + threadIdx.x;
    int c = t & (COUT - 1);
    float h = fmaf(g_sel[t], g_scale[c], g_shift[c]);
    out[t] = (h >= 0.0f) ? h : 0.2f*h;
}

extern "C" void kernel_launch(void* const* d_in, const int* in_sizes, int n_in,
                              void* d_out, int out_size) {
    const float* pos   = (const float*)d_in[0];
    const float* x     = (const float*)d_in[1];
    const float* W     = (const float*)d_in[2];
    const float* b     = (const float*)d_in[3];
    const float* gamma = (const float*)d_in[4];
    const float* beta  = (const float*)d_in[5];
    float* out = (float*)d_out;

    prep_kernel<<<256, 256>>>(pos, W);                         // 0
    knn_thresh_kernel<<<NP / 128, 128>>>();                    // 1
    knn_filter_kernel<<<dim3(NP / 256, NSLICE), 256>>>();      // 2
    knn_final_kernel<<<NP / 128, 128>>>();                     // 3
    gemm_kernel<<<dim3(WCOLS / 128, NP / 128), 256>>>(x, b);   // 4
    edge_kernel<<<NP / QPB, 128>>>(gamma);                     // 5
    finalize_kernel<<<1, COUT>>>(gamma, beta);                 // 6
    out_kernel<<<(NP * COUT) / 256, 256>>>(out);               // 7
}